// round 8
// baseline (speedup 1.0000x reference)
#include <cuda_runtime.h>

#define SQ 4096
#define DM 1024
#define NH 16
#define HDIM 64

// Scratch: head-major Q/K/V [H][S][64] and attention output [S][D].
// Referenced ONLY from device code (host-side symbol address is invalid).
__device__ float g_q[SQ * DM];
__device__ float g_k[SQ * DM];
__device__ float g_v[SQ * DM];
__device__ float g_ao[SQ * DM];

__device__ __forceinline__ unsigned f2tf(float f) {
    unsigned u;
    asm("cvt.rna.tf32.f32 %0, %1;" : "=r"(u) : "f"(f));
    return u;
}

__device__ __forceinline__ void mma_tf32(float* c, const unsigned* a, const unsigned* b) {
    asm("mma.sync.aligned.m16n8k8.row.col.f32.tf32.tf32.f32 "
        "{%0,%1,%2,%3},{%4,%5,%6,%7},{%8,%9},{%0,%1,%2,%3};"
        : "+f"(c[0]), "+f"(c[1]), "+f"(c[2]), "+f"(c[3])
        : "r"(a[0]), "r"(a[1]), "r"(a[2]), "r"(a[3]), "r"(b[0]), "r"(b[1]));
}

// ---------------------------------------------------------------------------
// Projection GEMM (R5 configuration — measured at the tf32 HMMA ceiling).
// CTA tile 128x128, Ktile 32, 8 warps (2m x 4n), register-prefetch pipeline.
// mode 0: A=A_ext (x), W per blockIdx.z, C = g_q/g_k/g_v head-major.
// mode 1: A=g_ao, W=W0 (Wo), C = C_ext (d_out) row-major.
// ---------------------------------------------------------------------------
__global__ __launch_bounds__(256) void proj_gemm(
    const float* __restrict__ A_ext,
    const float* __restrict__ W0, const float* __restrict__ W1,
    const float* __restrict__ W2,
    float* __restrict__ C_ext, int mode)
{
    __shared__ unsigned As[128 * 36];
    __shared__ unsigned Bs[128 * 36];

    const float* A;
    const float* W;
    float* C;
    if (mode == 0) {
        A = A_ext;
        W = (blockIdx.z == 0) ? W0 : ((blockIdx.z == 1) ? W1 : W2);
        C = (blockIdx.z == 0) ? g_q : ((blockIdx.z == 1) ? g_k : g_v);
    } else {
        A = g_ao;
        W = W0;
        C = C_ext;
    }

    const int tid = threadIdx.x;
    const int wid = tid >> 5, lane = tid & 31;
    const int g = lane >> 2, q = lane & 3;
    const int wm = (wid >> 2) * 64;
    const int wn = (wid & 3) * 32;
    const int row0 = blockIdx.x << 7;
    const int col0 = blockIdx.y << 7;
    const int lr = tid >> 3;             // 0..31
    const int lc = (tid & 7) << 2;       // 0..28

    float acc[4][4][4];
#pragma unroll
    for (int i = 0; i < 4; i++)
#pragma unroll
        for (int j = 0; j < 4; j++)
#pragma unroll
            for (int r = 0; r < 4; r++) acc[i][j][r] = 0.f;

    float4 apre[4], bpre[4];
#pragma unroll
    for (int c = 0; c < 4; c++) {
        int r = c * 32 + lr;
        apre[c] = *(const float4*)(A + (size_t)(row0 + r) * DM + lc);
        bpre[c] = *(const float4*)(W + (size_t)(col0 + r) * DM + lc);
    }

    for (int kt = 0; kt < DM; kt += 32) {
#pragma unroll
        for (int c = 0; c < 4; c++) {
            int r = c * 32 + lr;
            *(uint4*)&As[r * 36 + lc] =
                make_uint4(f2tf(apre[c].x), f2tf(apre[c].y), f2tf(apre[c].z), f2tf(apre[c].w));
            *(uint4*)&Bs[r * 36 + lc] =
                make_uint4(f2tf(bpre[c].x), f2tf(bpre[c].y), f2tf(bpre[c].z), f2tf(bpre[c].w));
        }
        __syncthreads();

        if (kt + 32 < DM) {
#pragma unroll
            for (int c = 0; c < 4; c++) {
                int r = c * 32 + lr;
                apre[c] = *(const float4*)(A + (size_t)(row0 + r) * DM + kt + 32 + lc);
                bpre[c] = *(const float4*)(W + (size_t)(col0 + r) * DM + kt + 32 + lc);
            }
        }

#pragma unroll
        for (int ks = 0; ks < 4; ks++) {
            unsigned af[4][4], bf[4][2];
#pragma unroll
            for (int mt = 0; mt < 4; mt++) {
                int base = (wm + mt * 16 + g) * 36 + ks * 8 + q;
                af[mt][0] = As[base];
                af[mt][1] = As[base + 8 * 36];
                af[mt][2] = As[base + 4];
                af[mt][3] = As[base + 8 * 36 + 4];
            }
#pragma unroll
            for (int nt = 0; nt < 4; nt++) {
                int base = (wn + nt * 8 + g) * 36 + ks * 8 + q;
                bf[nt][0] = Bs[base];
                bf[nt][1] = Bs[base + 4];
            }
#pragma unroll
            for (int mt = 0; mt < 4; mt++)
#pragma unroll
                for (int nt = 0; nt < 4; nt++)
                    mma_tf32(acc[mt][nt], af[mt], bf[nt]);
        }
        __syncthreads();
    }

#pragma unroll
    for (int mt = 0; mt < 4; mt++)
#pragma unroll
        for (int nt = 0; nt < 4; nt++) {
            int row = row0 + wm + mt * 16 + g;
            int col = col0 + wn + nt * 8 + 2 * q;
            if (mode == 0) {
                float* p0 = C + (size_t)(col >> 6) * SQ * HDIM + (size_t)row * HDIM + (col & 63);
                float* p1 = C + (size_t)(col >> 6) * SQ * HDIM + (size_t)(row + 8) * HDIM + (col & 63);
                p0[0] = acc[mt][nt][0]; p0[1] = acc[mt][nt][1];
                p1[0] = acc[mt][nt][2]; p1[1] = acc[mt][nt][3];
            } else {
                float* p0 = C + (size_t)row * DM + col;
                float* p1 = C + (size_t)(row + 8) * DM + col;
                p0[0] = acc[mt][nt][0]; p0[1] = acc[mt][nt][1];
                p1[0] = acc[mt][nt][2]; p1[1] = acc[mt][nt][3];
            }
        }
}

// ---------------------------------------------------------------------------
// Causal flash attention, tf32 tensor cores, Q tile = 128 rows per CTA.
// 256 threads = 8 warps; each warp owns 16 score rows x full 64 K-cols.
// Each 64-row K/V tile load now feeds 2x the MMA work vs the 64-row version
// (halved L2 traffic and barriers per FLOP). Per-row math order unchanged.
// Smem: Qs/Ps [128][68], Ks [64][68], Vt [64][72] (k-major V).
// ---------------------------------------------------------------------------
__global__ __launch_bounds__(256) void attn_kernel()
{
    extern __shared__ unsigned sm[];
    unsigned* Qs = sm;                           // [128][68], reused as Ps
    unsigned* Ks = sm + 128 * 68;                // [64][68]
    unsigned* Vt = sm + 128 * 68 + 64 * 68;      // [64][72] : Vt[k*72 + hd]
    unsigned* Ps = Qs;

    const int tid = threadIdx.x;
    const int wid = tid >> 5, lane = tid & 31;
    const int g = lane >> 2, q = lane & 3;
    const int wm = wid * 16;                     // 0..112
    const int qt = 31 - blockIdx.x;              // reversed: heavy tiles first
    const int h = blockIdx.y;
    const int lr = tid >> 4;                     // 0..15
    const int lc = (tid & 15) << 2;              // 0..60

    const float* Qh = g_q + (size_t)h * SQ * HDIM;
    const float* Kh = g_k + (size_t)h * SQ * HDIM;
    const float* Vh = g_v + (size_t)h * SQ * HDIM;

    // Q tile (128 rows) -> smem (tf32)
#pragma unroll
    for (int c = 0; c < 8; c++) {
        int r = c * 16 + lr;
        float4 v = *(const float4*)(Qh + (size_t)(qt * 128 + r) * HDIM + lc);
        *(uint4*)&Qs[r * 68 + lc] = make_uint4(f2tf(v.x), f2tf(v.y), f2tf(v.z), f2tf(v.w));
    }
    __syncthreads();

    // Q fragments -> registers (own-warp rows), invariant across jt
    unsigned qf[8][4];
#pragma unroll
    for (int ks = 0; ks < 8; ks++) {
        int base = (wm + g) * 68 + ks * 8 + q;
        qf[ks][0] = Qs[base];
        qf[ks][1] = Qs[base + 8 * 68];
        qf[ks][2] = Qs[base + 4];
        qf[ks][3] = Qs[base + 8 * 68 + 4];
    }

    float oacc[8][4];
#pragma unroll
    for (int nt = 0; nt < 8; nt++)
#pragma unroll
        for (int r = 0; r < 4; r++) oacc[nt][r] = 0.f;
    float m0 = -1e30f, m1 = -1e30f, l0 = 0.f, l1 = 0.f;
    const float scale = 0.125f;

    const int NJT = 2 * qt + 2;                  // K tiles covering causal extent
    const int rg0 = qt * 128 + wm + g;           // absolute row ids for masking
    const int rg1 = rg0 + 8;

    // prologue: prefetch jt=0 K/V tile (4 float4 each with 256 threads)
    float4 kpre[4], vpre[4];
#pragma unroll
    for (int c = 0; c < 4; c++) {
        int r = c * 16 + lr;
        kpre[c] = *(const float4*)(Kh + (size_t)r * HDIM + lc);
        vpre[c] = *(const float4*)(Vh + (size_t)r * HDIM + lc);
    }

    for (int jt = 0; jt < NJT; jt++) {
        __syncthreads();  // all warps done with prev Ks/Vt (and Qs frags on jt=0)
#pragma unroll
        for (int c = 0; c < 4; c++) {
            int r = c * 16 + lr;
            *(uint4*)&Ks[r * 68 + lc] =
                make_uint4(f2tf(kpre[c].x), f2tf(kpre[c].y), f2tf(kpre[c].z), f2tf(kpre[c].w));
            *(uint4*)&Vt[r * 72 + lc] =
                make_uint4(f2tf(vpre[c].x), f2tf(vpre[c].y), f2tf(vpre[c].z), f2tf(vpre[c].w));
        }
        __syncthreads();

        if (jt + 1 < NJT) {
#pragma unroll
            for (int c = 0; c < 4; c++) {
                int r = (jt + 1) * 64 + c * 16 + lr;
                kpre[c] = *(const float4*)(Kh + (size_t)r * HDIM + lc);
                vpre[c] = *(const float4*)(Vh + (size_t)r * HDIM + lc);
            }
        }

        // S = Q @ K^T  (warp: 16 x 64)
        float sa[8][4];
#pragma unroll
        for (int nt = 0; nt < 8; nt++)
#pragma unroll
            for (int r = 0; r < 4; r++) sa[nt][r] = 0.f;
#pragma unroll
        for (int ks = 0; ks < 8; ks++) {
            unsigned kf[8][2];
#pragma unroll
            for (int nt = 0; nt < 8; nt++) {
                int base = (nt * 8 + g) * 68 + ks * 8 + q;
                kf[nt][0] = Ks[base];
                kf[nt][1] = Ks[base + 4];
            }
#pragma unroll
            for (int nt = 0; nt < 8; nt++)
                mma_tf32(sa[nt], qf[ks], kf[nt]);
        }

        // scale + causal mask (absolute indices; only near-diagonal tiles mask)
        if (jt >= 2 * qt) {
#pragma unroll
            for (int nt = 0; nt < 8; nt++) {
                int c0 = jt * 64 + nt * 8 + 2 * q, c1 = c0 + 1;
                sa[nt][0] = (c0 > rg0) ? -1e30f : sa[nt][0] * scale;
                sa[nt][1] = (c1 > rg0) ? -1e30f : sa[nt][1] * scale;
                sa[nt][2] = (c0 > rg1) ? -1e30f : sa[nt][2] * scale;
                sa[nt][3] = (c1 > rg1) ? -1e30f : sa[nt][3] * scale;
            }
        } else {
#pragma unroll
            for (int nt = 0; nt < 8; nt++)
#pragma unroll
                for (int r = 0; r < 4; r++) sa[nt][r] *= scale;
        }

        // online softmax (quad shuffles; two rows per thread)
        float rm0 = -1e30f, rm1 = -1e30f;
#pragma unroll
        for (int nt = 0; nt < 8; nt++) {
            rm0 = fmaxf(rm0, fmaxf(sa[nt][0], sa[nt][1]));
            rm1 = fmaxf(rm1, fmaxf(sa[nt][2], sa[nt][3]));
        }
#pragma unroll
        for (int off = 1; off < 4; off <<= 1) {
            rm0 = fmaxf(rm0, __shfl_xor_sync(0xffffffffu, rm0, off));
            rm1 = fmaxf(rm1, __shfl_xor_sync(0xffffffffu, rm1, off));
        }
        float mn0 = fmaxf(m0, rm0), mn1 = fmaxf(m1, rm1);
        float al0 = __expf(m0 - mn0), al1 = __expf(m1 - mn1);
        m0 = mn0; m1 = mn1;
        float rs0 = 0.f, rs1 = 0.f;
#pragma unroll
        for (int nt = 0; nt < 8; nt++) {
            sa[nt][0] = __expf(sa[nt][0] - mn0);
            sa[nt][1] = __expf(sa[nt][1] - mn0);
            sa[nt][2] = __expf(sa[nt][2] - mn1);
            sa[nt][3] = __expf(sa[nt][3] - mn1);
            rs0 += sa[nt][0] + sa[nt][1];
            rs1 += sa[nt][2] + sa[nt][3];
        }
#pragma unroll
        for (int off = 1; off < 4; off <<= 1) {
            rs0 += __shfl_xor_sync(0xffffffffu, rs0, off);
            rs1 += __shfl_xor_sync(0xffffffffu, rs1, off);
        }
        l0 = l0 * al0 + rs0;
        l1 = l1 * al1 + rs1;
#pragma unroll
        for (int nt = 0; nt < 8; nt++) {
            oacc[nt][0] *= al0; oacc[nt][1] *= al0;
            oacc[nt][2] *= al1; oacc[nt][3] *= al1;
        }

        // P -> smem (tf32), own-warp rows only
#pragma unroll
        for (int nt = 0; nt < 8; nt++) {
            int a0 = (wm + g) * 68 + nt * 8 + 2 * q;
            int a1 = (wm + g + 8) * 68 + nt * 8 + 2 * q;
            Ps[a0] = f2tf(sa[nt][0]); Ps[a0 + 1] = f2tf(sa[nt][1]);
            Ps[a1] = f2tf(sa[nt][2]); Ps[a1 + 1] = f2tf(sa[nt][3]);
        }
        __syncwarp();

        // O += P @ V  (warp: 16 x 64)
#pragma unroll
        for (int ks = 0; ks < 8; ks++) {
            unsigned pf[4];
            int base = (wm + g) * 68 + ks * 8 + q;
            pf[0] = Ps[base];
            pf[1] = Ps[base + 8 * 68];
            pf[2] = Ps[base + 4];
            pf[3] = Ps[base + 8 * 68 + 4];
#pragma unroll
            for (int nt = 0; nt < 8; nt++) {
                unsigned vb[2];
                int vbase = (ks * 8 + q) * 72 + nt * 8 + g;
                vb[0] = Vt[vbase];
                vb[1] = Vt[vbase + 4 * 72];
                mma_tf32(oacc[nt], pf, vb);
            }
        }
    }

    // epilogue: normalize, write [s][d] for the output projection
    float inv0 = 1.f / l0, inv1 = 1.f / l1;
#pragma unroll
    for (int nt = 0; nt < 8; nt++) {
        int row = qt * 128 + wm + g;
        int col = h * HDIM + nt * 8 + 2 * q;
        float* p0 = g_ao + (size_t)row * DM + col;
        float* p1 = g_ao + (size_t)(row + 8) * DM + col;
        p0[0] = oacc[nt][0] * inv0; p0[1] = oacc[nt][1] * inv0;
        p1[0] = oacc[nt][2] * inv1; p1[1] = oacc[nt][3] * inv1;
    }
}

// ---------------------------------------------------------------------------
// inputs: 0=x, 1=mask (ignored; causal structural), 2=Wq, 3=Wk, 4=Wv, 5=Wo
// ---------------------------------------------------------------------------
extern "C" void kernel_launch(void* const* d_in, const int* in_sizes, int n_in,
                              void* d_out, int out_size)
{
    const float* x  = (const float*)d_in[0];
    const float* Wq = (const float*)d_in[2];
    const float* Wk = (const float*)d_in[3];
    const float* Wv = (const float*)d_in[4];
    const float* Wo = (const float*)d_in[5];
    float* out = (float*)d_out;

    // attn smem: (128*68 + 64*68 + 64*72) * 4 = 70656 B
    cudaFuncSetAttribute(attn_kernel,
                         cudaFuncAttributeMaxDynamicSharedMemorySize, 70656);

    dim3 gq(SQ / 128, DM / 128, 3);
    proj_gemm<<<gq, 256>>>(x, Wq, Wk, Wv, nullptr, 0);

    dim3 ga(SQ / 128, NH);
    attn_kernel<<<ga, 256, 70656>>>();

    dim3 go(SQ / 128, DM / 128, 1);
    proj_gemm<<<go, 256>>>(nullptr, Wo, nullptr, nullptr, out, 1);
}

// round 9
// speedup vs baseline: 1.0433x; 1.0433x over previous
#include <cuda_runtime.h>

#define SQ 4096
#define DM 1024
#define NH 16
#define HDIM 64

// Scratch: head-major Q/K/V [H][S][64] and attention output [S][D].
// Referenced ONLY from device code (host-side symbol address is invalid).
__device__ float g_q[SQ * DM];
__device__ float g_k[SQ * DM];
__device__ float g_v[SQ * DM];
__device__ float g_ao[SQ * DM];

__device__ __forceinline__ unsigned f2tf(float f) {
    unsigned u;
    asm("cvt.rna.tf32.f32 %0, %1;" : "=r"(u) : "f"(f));
    return u;
}

__device__ __forceinline__ void mma_tf32(float* c, const unsigned* a, const unsigned* b) {
    asm("mma.sync.aligned.m16n8k8.row.col.f32.tf32.tf32.f32 "
        "{%0,%1,%2,%3},{%4,%5,%6,%7},{%8,%9},{%0,%1,%2,%3};"
        : "+f"(c[0]), "+f"(c[1]), "+f"(c[2]), "+f"(c[3])
        : "r"(a[0]), "r"(a[1]), "r"(a[2]), "r"(a[3]), "r"(b[0]), "r"(b[1]));
}

__device__ __forceinline__ void ldsm4(unsigned* r, const unsigned* p) {
    unsigned addr = (unsigned)__cvta_generic_to_shared(p);
    asm volatile("ldmatrix.sync.aligned.m8n8.x4.shared.b16 {%0,%1,%2,%3}, [%4];"
                 : "=r"(r[0]), "=r"(r[1]), "=r"(r[2]), "=r"(r[3]) : "r"(addr));
}

// ---------------------------------------------------------------------------
// Projection GEMM (R5 configuration — measured at the tf32 HMMA ceiling).
// CTA tile 128x128, Ktile 32, 8 warps (2m x 4n), register-prefetch pipeline,
// static smem (keeps 2 CTAs/SM).
// mode 0: A=A_ext (x), W per blockIdx.z, C = g_q/g_k/g_v head-major.
// mode 1: A=g_ao, W=W0 (Wo), C = C_ext (d_out) row-major.
// ---------------------------------------------------------------------------
__global__ __launch_bounds__(256) void proj_gemm(
    const float* __restrict__ A_ext,
    const float* __restrict__ W0, const float* __restrict__ W1,
    const float* __restrict__ W2,
    float* __restrict__ C_ext, int mode)
{
    __shared__ unsigned As[128 * 36];
    __shared__ unsigned Bs[128 * 36];

    const float* A;
    const float* W;
    float* C;
    if (mode == 0) {
        A = A_ext;
        W = (blockIdx.z == 0) ? W0 : ((blockIdx.z == 1) ? W1 : W2);
        C = (blockIdx.z == 0) ? g_q : ((blockIdx.z == 1) ? g_k : g_v);
    } else {
        A = g_ao;
        W = W0;
        C = C_ext;
    }

    const int tid = threadIdx.x;
    const int wid = tid >> 5, lane = tid & 31;
    const int g = lane >> 2, q = lane & 3;
    const int wm = (wid >> 2) * 64;
    const int wn = (wid & 3) * 32;
    const int row0 = blockIdx.x << 7;
    const int col0 = blockIdx.y << 7;
    const int lr = tid >> 3;
    const int lc = (tid & 7) << 2;

    float acc[4][4][4];
#pragma unroll
    for (int i = 0; i < 4; i++)
#pragma unroll
        for (int j = 0; j < 4; j++)
#pragma unroll
            for (int r = 0; r < 4; r++) acc[i][j][r] = 0.f;

    float4 apre[4], bpre[4];
#pragma unroll
    for (int c = 0; c < 4; c++) {
        int r = c * 32 + lr;
        apre[c] = *(const float4*)(A + (size_t)(row0 + r) * DM + lc);
        bpre[c] = *(const float4*)(W + (size_t)(col0 + r) * DM + lc);
    }

    for (int kt = 0; kt < DM; kt += 32) {
#pragma unroll
        for (int c = 0; c < 4; c++) {
            int r = c * 32 + lr;
            *(uint4*)&As[r * 36 + lc] =
                make_uint4(f2tf(apre[c].x), f2tf(apre[c].y), f2tf(apre[c].z), f2tf(apre[c].w));
            *(uint4*)&Bs[r * 36 + lc] =
                make_uint4(f2tf(bpre[c].x), f2tf(bpre[c].y), f2tf(bpre[c].z), f2tf(bpre[c].w));
        }
        __syncthreads();

        if (kt + 32 < DM) {
#pragma unroll
            for (int c = 0; c < 4; c++) {
                int r = c * 32 + lr;
                apre[c] = *(const float4*)(A + (size_t)(row0 + r) * DM + kt + 32 + lc);
                bpre[c] = *(const float4*)(W + (size_t)(col0 + r) * DM + kt + 32 + lc);
            }
        }

#pragma unroll
        for (int ks = 0; ks < 4; ks++) {
            unsigned af[4][4], bf[4][2];
#pragma unroll
            for (int mt = 0; mt < 4; mt++) {
                int base = (wm + mt * 16 + g) * 36 + ks * 8 + q;
                af[mt][0] = As[base];
                af[mt][1] = As[base + 8 * 36];
                af[mt][2] = As[base + 4];
                af[mt][3] = As[base + 8 * 36 + 4];
            }
#pragma unroll
            for (int nt = 0; nt < 4; nt++) {
                int base = (wn + nt * 8 + g) * 36 + ks * 8 + q;
                bf[nt][0] = Bs[base];
                bf[nt][1] = Bs[base + 4];
            }
#pragma unroll
            for (int mt = 0; mt < 4; mt++)
#pragma unroll
                for (int nt = 0; nt < 4; nt++)
                    mma_tf32(acc[mt][nt], af[mt], bf[nt]);
        }
        __syncthreads();
    }

#pragma unroll
    for (int mt = 0; mt < 4; mt++)
#pragma unroll
        for (int nt = 0; nt < 4; nt++) {
            int row = row0 + wm + mt * 16 + g;
            int col = col0 + wn + nt * 8 + 2 * q;
            if (mode == 0) {
                float* p0 = C + (size_t)(col >> 6) * SQ * HDIM + (size_t)row * HDIM + (col & 63);
                float* p1 = C + (size_t)(col >> 6) * SQ * HDIM + (size_t)(row + 8) * HDIM + (col & 63);
                p0[0] = acc[mt][nt][0]; p0[1] = acc[mt][nt][1];
                p1[0] = acc[mt][nt][2]; p1[1] = acc[mt][nt][3];
            } else {
                float* p0 = C + (size_t)row * DM + col;
                float* p1 = C + (size_t)(row + 8) * DM + col;
                p0[0] = acc[mt][nt][0]; p0[1] = acc[mt][nt][1];
                p1[0] = acc[mt][nt][2]; p1[1] = acc[mt][nt][3];
            }
        }
}

// ---------------------------------------------------------------------------
// Causal flash attention, tf32 tensor cores (R6 attention config: ldmatrix
// fragments + 2-stage K/V double buffer, one barrier per iteration).
// Softmax in log2 domain: scores scaled by scale*log2e, exp2f (bare EX2).
// 128 threads = 4 warps; warp owns 16 score rows x 64 cols, TILE_Q = 64.
// Smem: Qs/Ps [64][68], Ks 2x[64][68], Vt 2x[64][72].
// ---------------------------------------------------------------------------
__global__ __launch_bounds__(128) void attn_kernel()
{
    extern __shared__ unsigned sm[];
    unsigned* Qs = sm;                       // [64][68], reused as Ps
    unsigned* Ks = sm + 64 * 68;             // 2 stages x [64][68]
    unsigned* Vt = sm + 3 * 64 * 68;         // 2 stages x [64][72]
    unsigned* Ps = Qs;

    const int tid = threadIdx.x;
    const int wid = tid >> 5, lane = tid & 31;
    const int g = lane >> 2, q = lane & 3;
    const int wm = wid * 16;
    const int qt = 63 - blockIdx.x;          // heavy tiles first
    const int h = blockIdx.y;
    const int lr = tid >> 4;                 // 0..7
    const int lc = (tid & 15) << 2;          // 0..60

    const int trow = lane & 15;              // ldmatrix A-pattern (Q/P frags)
    const int tcol = (lane >> 4) * 4;
    const int bseg = lane >> 3;              // ldmatrix B-pattern (K frags)
    const int brow = ((bseg >= 2) ? 8 : 0) + (lane & 7);
    const int bcol = (bseg & 1) * 4;

    const float* Qh = g_q + (size_t)h * SQ * HDIM;
    const float* Kh = g_k + (size_t)h * SQ * HDIM;
    const float* Vh = g_v + (size_t)h * SQ * HDIM;

#pragma unroll
    for (int c = 0; c < 8; c++) {
        int r = c * 8 + lr;
        float4 v = *(const float4*)(Qh + (size_t)(qt * 64 + r) * HDIM + lc);
        *(uint4*)&Qs[r * 68 + lc] = make_uint4(f2tf(v.x), f2tf(v.y), f2tf(v.z), f2tf(v.w));
    }
    __syncthreads();

    unsigned qf[8][4];
#pragma unroll
    for (int ks = 0; ks < 8; ks++)
        ldsm4(qf[ks], &Qs[(wm + trow) * 68 + ks * 8 + tcol]);

    float oacc[8][4];
#pragma unroll
    for (int nt = 0; nt < 8; nt++)
#pragma unroll
        for (int r = 0; r < 4; r++) oacc[nt][r] = 0.f;
    float m0 = -1e30f, m1 = -1e30f, l0 = 0.f, l1 = 0.f;
    const float cl2 = 0.125f * 1.44269504f;  // scale * log2(e): log2-domain softmax

    float4 kpre[8], vpre[8];
#pragma unroll
    for (int c = 0; c < 8; c++) {
        int r = c * 8 + lr;
        kpre[c] = *(const float4*)(Kh + (size_t)r * HDIM + lc);
        vpre[c] = *(const float4*)(Vh + (size_t)r * HDIM + lc);
    }
#pragma unroll
    for (int c = 0; c < 8; c++) {
        int r = c * 8 + lr;
        *(uint4*)&Ks[r * 68 + lc] =
            make_uint4(f2tf(kpre[c].x), f2tf(kpre[c].y), f2tf(kpre[c].z), f2tf(kpre[c].w));
        *(uint4*)&Vt[r * 72 + lc] =
            make_uint4(f2tf(vpre[c].x), f2tf(vpre[c].y), f2tf(vpre[c].z), f2tf(vpre[c].w));
    }

    for (int jt = 0; jt <= qt; jt++) {
        unsigned* ks_s = Ks + (jt & 1) * 64 * 68;
        unsigned* vt_s = Vt + (jt & 1) * 64 * 72;
        __syncthreads();   // stage (jt&1) committed; prior consumers done

        if (jt < qt) {
#pragma unroll
            for (int c = 0; c < 8; c++) {
                int r = (jt + 1) * 64 + c * 8 + lr;
                kpre[c] = *(const float4*)(Kh + (size_t)r * HDIM + lc);
                vpre[c] = *(const float4*)(Vh + (size_t)r * HDIM + lc);
            }
        }

        // S = Q @ K^T  (warp: 16 x 64)
        float sa[8][4];
#pragma unroll
        for (int nt = 0; nt < 8; nt++)
#pragma unroll
            for (int r = 0; r < 4; r++) sa[nt][r] = 0.f;
#pragma unroll
        for (int ks = 0; ks < 8; ks++) {
            unsigned kf[8][2];
#pragma unroll
            for (int ntp = 0; ntp < 8; ntp += 2) {
                unsigned t4[4];
                ldsm4(t4, &ks_s[(ntp * 8 + brow) * 68 + ks * 8 + bcol]);
                kf[ntp][0] = t4[0]; kf[ntp][1] = t4[1];
                kf[ntp + 1][0] = t4[2]; kf[ntp + 1][1] = t4[3];
            }
#pragma unroll
            for (int nt = 0; nt < 8; nt++)
                mma_tf32(sa[nt], qf[ks], kf[nt]);
        }

        // scale into log2 domain + causal mask (diag tile only)
        if (jt == qt) {
            int r0 = wm + g, r1 = wm + g + 8;
#pragma unroll
            for (int nt = 0; nt < 8; nt++) {
                int c0 = nt * 8 + 2 * q, c1 = c0 + 1;
                sa[nt][0] = (c0 > r0) ? -1e30f : sa[nt][0] * cl2;
                sa[nt][1] = (c1 > r0) ? -1e30f : sa[nt][1] * cl2;
                sa[nt][2] = (c0 > r1) ? -1e30f : sa[nt][2] * cl2;
                sa[nt][3] = (c1 > r1) ? -1e30f : sa[nt][3] * cl2;
            }
        } else {
#pragma unroll
            for (int nt = 0; nt < 8; nt++)
#pragma unroll
                for (int r = 0; r < 4; r++) sa[nt][r] *= cl2;
        }

        // online softmax in log2 domain (quad shuffles)
        float rm0 = -1e30f, rm1 = -1e30f;
#pragma unroll
        for (int nt = 0; nt < 8; nt++) {
            rm0 = fmaxf(rm0, fmaxf(sa[nt][0], sa[nt][1]));
            rm1 = fmaxf(rm1, fmaxf(sa[nt][2], sa[nt][3]));
        }
#pragma unroll
        for (int off = 1; off < 4; off <<= 1) {
            rm0 = fmaxf(rm0, __shfl_xor_sync(0xffffffffu, rm0, off));
            rm1 = fmaxf(rm1, __shfl_xor_sync(0xffffffffu, rm1, off));
        }
        float mn0 = fmaxf(m0, rm0), mn1 = fmaxf(m1, rm1);
        float al0 = exp2f(m0 - mn0), al1 = exp2f(m1 - mn1);
        m0 = mn0; m1 = mn1;
        float rs0 = 0.f, rs1 = 0.f;
#pragma unroll
        for (int nt = 0; nt < 8; nt++) {
            sa[nt][0] = exp2f(sa[nt][0] - mn0);
            sa[nt][1] = exp2f(sa[nt][1] - mn0);
            sa[nt][2] = exp2f(sa[nt][2] - mn1);
            sa[nt][3] = exp2f(sa[nt][3] - mn1);
            rs0 += sa[nt][0] + sa[nt][1];
            rs1 += sa[nt][2] + sa[nt][3];
        }
#pragma unroll
        for (int off = 1; off < 4; off <<= 1) {
            rs0 += __shfl_xor_sync(0xffffffffu, rs0, off);
            rs1 += __shfl_xor_sync(0xffffffffu, rs1, off);
        }
        l0 = l0 * al0 + rs0;
        l1 = l1 * al1 + rs1;
#pragma unroll
        for (int nt = 0; nt < 8; nt++) {
            oacc[nt][0] *= al0; oacc[nt][1] *= al0;
            oacc[nt][2] *= al1; oacc[nt][3] *= al1;
        }

        // P -> smem (tf32), own-warp rows only
#pragma unroll
        for (int nt = 0; nt < 8; nt++) {
            int a0 = (wm + g) * 68 + nt * 8 + 2 * q;
            int a1 = (wm + g + 8) * 68 + nt * 8 + 2 * q;
            Ps[a0] = f2tf(sa[nt][0]); Ps[a0 + 1] = f2tf(sa[nt][1]);
            Ps[a1] = f2tf(sa[nt][2]); Ps[a1 + 1] = f2tf(sa[nt][3]);
        }
        __syncwarp();

        // O += P @ V  (warp: 16 x 64); P frags ldmatrix, V frags scalar
#pragma unroll
        for (int ks = 0; ks < 8; ks++) {
            unsigned pf[4];
            ldsm4(pf, &Ps[(wm + trow) * 68 + ks * 8 + tcol]);
#pragma unroll
            for (int nt = 0; nt < 8; nt++) {
                unsigned vb[2];
                int vbase = (ks * 8 + q) * 72 + nt * 8 + g;
                vb[0] = vt_s[vbase];
                vb[1] = vt_s[vbase + 4 * 72];
                mma_tf32(oacc[nt], pf, vb);
            }
        }

        // commit next tile to the other stage (consumed after next barrier)
        if (jt < qt) {
            unsigned* ks_n = Ks + ((jt + 1) & 1) * 64 * 68;
            unsigned* vt_n = Vt + ((jt + 1) & 1) * 64 * 72;
#pragma unroll
            for (int c = 0; c < 8; c++) {
                int r = c * 8 + lr;
                *(uint4*)&ks_n[r * 68 + lc] =
                    make_uint4(f2tf(kpre[c].x), f2tf(kpre[c].y), f2tf(kpre[c].z), f2tf(kpre[c].w));
                *(uint4*)&vt_n[r * 72 + lc] =
                    make_uint4(f2tf(vpre[c].x), f2tf(vpre[c].y), f2tf(vpre[c].z), f2tf(vpre[c].w));
            }
        }
    }

    // epilogue: normalize, write [s][d] for the output projection
    float inv0 = 1.f / l0, inv1 = 1.f / l1;
#pragma unroll
    for (int nt = 0; nt < 8; nt++) {
        int row = qt * 64 + wm + g;
        int col = h * HDIM + nt * 8 + 2 * q;
        float* p0 = g_ao + (size_t)row * DM + col;
        float* p1 = g_ao + (size_t)(row + 8) * DM + col;
        p0[0] = oacc[nt][0] * inv0; p0[1] = oacc[nt][1] * inv0;
        p1[0] = oacc[nt][2] * inv1; p1[1] = oacc[nt][3] * inv1;
    }
}

// ---------------------------------------------------------------------------
// inputs: 0=x, 1=mask (ignored; causal structural), 2=Wq, 3=Wk, 4=Wv, 5=Wo
// ---------------------------------------------------------------------------
extern "C" void kernel_launch(void* const* d_in, const int* in_sizes, int n_in,
                              void* d_out, int out_size)
{
    const float* x  = (const float*)d_in[0];
    const float* Wq = (const float*)d_in[2];
    const float* Wk = (const float*)d_in[3];
    const float* Wv = (const float*)d_in[4];
    const float* Wo = (const float*)d_in[5];
    float* out = (float*)d_out;

    // attn smem: (64*68 + 2*64*68 + 2*64*72) * 4 = 89088 B
    cudaFuncSetAttribute(attn_kernel,
                         cudaFuncAttributeMaxDynamicSharedMemorySize, 89088);

    dim3 gq(SQ / 128, DM / 128, 3);
    proj_gemm<<<gq, 256>>>(x, Wq, Wk, Wv, nullptr, 0);

    dim3 ga(SQ / 64, NH);
    attn_kernel<<<ga, 128, 89088>>>();

    dim3 go(SQ / 128, DM / 128, 1);
    proj_gemm<<<go, 256>>>(nullptr, Wo, nullptr, nullptr, out, 1);
}